// round 10
// baseline (speedup 1.0000x reference)
#include <cuda_runtime.h>
#include <cstdint>

// RoiAlign (crop_and_resize, bilinear, extrapolation=0) with 2-level FPN select.
// feat0: [2,256,256,256] f32, feat1: [2,128,128,256] f32, rois: [2,512,5] f32
// out:   [2,512,7,7,256] f32
//
// Mapping: one WARP per output ROW (box, py) = 7 pooled cells. Each lane holds
// 8 channels (2x float4). The two bilinear y-rows are fixed per warp; corner
// COLUMNS are cached in registers and reused across px when the floor() x
// indices of consecutive cells coincide (warp-uniform control flow).

#define NUM_B 2
#define NUM_R 512
#define CCH 256
#define POOL 7
#define CELLS_PER_BOX (POOL * POOL)
#define INV_IMG (1.0f / 1024.0f)
#define LVL_THRESH 48.0f

__device__ __forceinline__ float4 lerp4(float4 a, float4 b, float w) {
    return make_float4(fmaf(b.x - a.x, w, a.x),
                       fmaf(b.y - a.y, w, a.y),
                       fmaf(b.z - a.z, w, a.z),
                       fmaf(b.w - a.w, w, a.w));
}

__global__ __launch_bounds__(256) void roialign_kernel(
    const float4* __restrict__ feat0,
    const float4* __restrict__ feat1,
    const float* __restrict__ rois,
    float4* __restrict__ out,
    int n_rows)
{
    const int warpId = threadIdx.x >> 5;
    const int lane   = threadIdx.x & 31;
    const int rowId  = blockIdx.x * 8 + warpId;     // (box, py)
    if (rowId >= n_rows) return;

    const int box = rowId / POOL;
    const int py  = rowId - box * POOL;
    const int b   = box >> 9;                        // box / 512

    const float* roi = rois + box * 5;
    const float y1 = roi[0];
    const float x1 = roi[1];
    const float y2 = roi[2];
    const float x2 = roi[3];

    const bool lvl1 = ((y2 - y1) > LVL_THRESH) || ((x2 - x1) > LVL_THRESH);
    const float4* __restrict__ img4 = lvl1 ? feat1 : feat0;
    const int HW = lvl1 ? 128 : 256;                 // H == W at both levels
    const float HWm1 = (float)(HW - 1);

    float4* outp = out + (box * CELLS_PER_BOX + py * POOL) * (CCH / 4) + lane * 2;
    const float4 z = make_float4(0.f, 0.f, 0.f, 0.f);

    // y sample (identical arithmetic to the previously-passing kernel)
    const float ry = (float)py * (1.0f / 6.0f);
    const float ys = (y1 * INV_IMG + ry * (y2 - y1) * INV_IMG) * HWm1;
    if (!(ys >= 0.0f && ys <= HWm1)) {
        #pragma unroll
        for (int px = 0; px < POOL; ++px, outp += CCH / 4) {
            outp[0] = z;
            outp[1] = z;
        }
        return;
    }
    const float y0f = floorf(ys);
    const float wy  = ys - y0f;
    const int iy0 = (int)y0f;
    const int iyp = min(iy0 + 1, HW - 1);

    const float4* __restrict__ prow0 = img4 + ((b * HW + iy0) * HW) * (CCH / 4) + lane * 2;
    const float4* __restrict__ prow1 = img4 + ((b * HW + iyp) * HW) * (CCH / 4) + lane * 2;

    // Register-cached corner columns: L = left corner column, R = right.
    // {L,R}{00,01} = y-row0 two float4s, {L,R}{10,11} = y-row1 two float4s.
    float4 L00, L01, L10, L11;
    float4 R00, R01, R10, R11;
    int lastL = -1, lastR = -1;

    #pragma unroll
    for (int px = 0; px < POOL; ++px, outp += CCH / 4) {
        const float rx = (float)px * (1.0f / 6.0f);
        const float xs = (x1 * INV_IMG + rx * (x2 - x1) * INV_IMG) * HWm1;
        if (!(xs >= 0.0f && xs <= HWm1)) {
            outp[0] = z;
            outp[1] = z;
            continue;
        }
        const float x0f = floorf(xs);
        const float wx  = xs - x0f;
        const int ix0 = (int)x0f;
        const int ixp = min(ix0 + 1, HW - 1);

        // Left column: reuse previous right (common forward step) or previous left.
        if (ix0 == lastR) {
            L00 = R00; L01 = R01; L10 = R10; L11 = R11;
        } else if (ix0 != lastL) {
            const float4* p0 = prow0 + ix0 * (CCH / 4);
            const float4* p1 = prow1 + ix0 * (CCH / 4);
            L00 = p0[0]; L01 = p0[1];
            L10 = p1[0]; L11 = p1[1];
        }
        lastL = ix0;

        // Right column: degenerate clamp (ixp==ix0) copies L, else reuse or load.
        if (ixp == ix0) {
            R00 = L00; R01 = L01; R10 = L10; R11 = L11;
        } else if (ixp != lastR) {
            const float4* p0 = prow0 + ixp * (CCH / 4);
            const float4* p1 = prow1 + ixp * (CCH / 4);
            R00 = p0[0]; R01 = p0[1];
            R10 = p1[0]; R11 = p1[1];
        }
        lastR = ixp;

        const float4 r0 = lerp4(lerp4(L00, R00, wx), lerp4(L10, R10, wx), wy);
        const float4 r1 = lerp4(lerp4(L01, R01, wx), lerp4(L11, R11, wx), wy);
        outp[0] = r0;
        outp[1] = r1;
    }
}

extern "C" void kernel_launch(void* const* d_in, const int* in_sizes, int n_in,
                              void* d_out, int out_size) {
    const float4* feat0 = (const float4*)d_in[0];
    const float4* feat1 = (const float4*)d_in[1];
    const float* rois   = (const float*)d_in[2];
    float4* out = (float4*)d_out;

    const int n_rows = NUM_B * NUM_R * POOL;        // 7168 warp-rows
    const int blocks = (n_rows + 7) / 8;            // 8 warps per 256-thread block
    roialign_kernel<<<blocks, 256>>>(feat0, feat1, rois, out, n_rows);
}

// round 11
// speedup vs baseline: 1.0326x; 1.0326x over previous
#include <cuda_runtime.h>
#include <cstdint>

// RoiAlign (crop_and_resize, bilinear, extrapolation=0) with 2-level FPN select.
// feat0: [2,256,256,256] f32, feat1: [2,128,128,256] f32, rois: [2,512,5] f32
// out:   [2,512,7,7,256] f32
//
// Mapping: one WARP per (box, py, channel-half). Lane = one float4 (4 channels);
// 32 lanes x 4 = 128 channels, 2 warps cover the 256 channels of one output row.
// The two bilinear y-rows are fixed per warp; corner COLUMNS (2 float4s each:
// row0+row1) are cached in registers and reused across px when floor() x
// indices repeat (warp-uniform control flow, no divergence).

#define NUM_B 2
#define NUM_R 512
#define CCH 256
#define POOL 7
#define CELLS_PER_BOX (POOL * POOL)
#define INV_IMG (1.0f / 1024.0f)
#define LVL_THRESH 48.0f

__device__ __forceinline__ float4 lerp4(float4 a, float4 b, float w) {
    return make_float4(fmaf(b.x - a.x, w, a.x),
                       fmaf(b.y - a.y, w, a.y),
                       fmaf(b.z - a.z, w, a.z),
                       fmaf(b.w - a.w, w, a.w));
}

__global__ __launch_bounds__(256, 5) void roialign_kernel(
    const float4* __restrict__ feat0,
    const float4* __restrict__ feat1,
    const float* __restrict__ rois,
    float4* __restrict__ out,
    int n_tasks)
{
    const int warpId = threadIdx.x >> 5;
    const int lane   = threadIdx.x & 31;
    const int task   = blockIdx.x * 8 + warpId;      // (box, py, half)
    if (task >= n_tasks) return;

    const int rowId = task >> 1;                     // (box, py)
    const int half  = task & 1;                      // channel half
    const int box = rowId / POOL;
    const int py  = rowId - box * POOL;
    const int b   = box >> 9;                        // box / 512

    const float* roi = rois + box * 5;
    const float y1 = roi[0];
    const float x1 = roi[1];
    const float y2 = roi[2];
    const float x2 = roi[3];

    const bool lvl1 = ((y2 - y1) > LVL_THRESH) || ((x2 - x1) > LVL_THRESH);
    const float4* __restrict__ img4 = lvl1 ? feat1 : feat0;
    const int HW = lvl1 ? 128 : 256;                 // H == W at both levels
    const float HWm1 = (float)(HW - 1);

    const int ch = half * 32 + lane;                 // float4 index within pixel
    float4* outp = out + (box * CELLS_PER_BOX + py * POOL) * (CCH / 4) + ch;
    const float4 z = make_float4(0.f, 0.f, 0.f, 0.f);

    // y sample (identical arithmetic to the passing kernels)
    const float ry = (float)py * (1.0f / 6.0f);
    const float ys = (y1 * INV_IMG + ry * (y2 - y1) * INV_IMG) * HWm1;
    if (!(ys >= 0.0f && ys <= HWm1)) {
        #pragma unroll
        for (int px = 0; px < POOL; ++px, outp += CCH / 4)
            *outp = z;
        return;
    }
    const float y0f = floorf(ys);
    const float wy  = ys - y0f;
    const int iy0 = (int)y0f;
    const int iyp = min(iy0 + 1, HW - 1);

    const float4* __restrict__ prow0 = img4 + ((b * HW + iy0) * HW) * (CCH / 4) + ch;
    const float4* __restrict__ prow1 = img4 + ((b * HW + iyp) * HW) * (CCH / 4) + ch;

    // Register-cached corner columns: L = left, R = right; each holds (row0,row1).
    float4 La, Lb;      // La = row0 at ix0, Lb = row1 at ix0
    float4 Ra, Rb;      // Ra = row0 at ixp, Rb = row1 at ixp
    int lastL = -1, lastR = -1;

    #pragma unroll
    for (int px = 0; px < POOL; ++px, outp += CCH / 4) {
        const float rx = (float)px * (1.0f / 6.0f);
        const float xs = (x1 * INV_IMG + rx * (x2 - x1) * INV_IMG) * HWm1;
        if (!(xs >= 0.0f && xs <= HWm1)) {
            *outp = z;
            continue;
        }
        const float x0f = floorf(xs);
        const float wx  = xs - x0f;
        const int ix0 = (int)x0f;
        const int ixp = min(ix0 + 1, HW - 1);

        // Left column: reuse previous right (common forward step) or previous left.
        if (ix0 == lastR) {
            La = Ra; Lb = Rb;
        } else if (ix0 != lastL) {
            La = prow0[ix0 * (CCH / 4)];
            Lb = prow1[ix0 * (CCH / 4)];
        }
        lastL = ix0;

        // Right column: degenerate clamp copies L, else reuse or load.
        if (ixp == ix0) {
            Ra = La; Rb = Lb;
        } else if (ixp != lastR) {
            Ra = prow0[ixp * (CCH / 4)];
            Rb = prow1[ixp * (CCH / 4)];
        }
        lastR = ixp;

        *outp = lerp4(lerp4(La, Ra, wx), lerp4(Lb, Rb, wx), wy);
    }
}

extern "C" void kernel_launch(void* const* d_in, const int* in_sizes, int n_in,
                              void* d_out, int out_size) {
    const float4* feat0 = (const float4*)d_in[0];
    const float4* feat1 = (const float4*)d_in[1];
    const float* rois   = (const float*)d_in[2];
    float4* out = (float4*)d_out;

    const int n_tasks = NUM_B * NUM_R * POOL * 2;    // 14336 warp-tasks
    const int blocks = (n_tasks + 7) / 8;            // 8 warps per 256-thread block
    roialign_kernel<<<blocks, 256>>>(feat0, feat1, rois, out, n_tasks);
}

// round 14
// speedup vs baseline: 1.2624x; 1.2225x over previous
#include <cuda_runtime.h>
#include <cstdint>

// RoiAlign (crop_and_resize, bilinear, extrapolation=0) with 2-level FPN select.
// feat0: [2,256,256,256] f32, feat1: [2,128,128,256] f32, rois: [2,512,5] f32
// out:   [2,512,7,7,256] f32
//
// Mapping: one WARP per pooled cell; each lane handles 8 channels (2x float4),
// 8 fully-independent LDG.128 per thread (max MLP). 4 warps (4 cells) per
// 128-thread block; __launch_bounds__(128,12) -> 48 warps/SM occupancy cap.

#define NUM_B 2
#define NUM_R 512
#define CCH 256
#define POOL 7
#define CELLS_PER_BOX (POOL * POOL)
#define INV_IMG (1.0f / 1024.0f)
#define LVL_THRESH 48.0f

__device__ __forceinline__ float4 lerp4(float4 a, float4 b, float w) {
    return make_float4(fmaf(b.x - a.x, w, a.x),
                       fmaf(b.y - a.y, w, a.y),
                       fmaf(b.z - a.z, w, a.z),
                       fmaf(b.w - a.w, w, a.w));
}

__global__ __launch_bounds__(128, 12) void roialign_kernel(
    const float4* __restrict__ feat0,
    const float4* __restrict__ feat1,
    const float* __restrict__ rois,
    float4* __restrict__ out)
{
    const int warpId = threadIdx.x >> 5;
    const int lane   = threadIdx.x & 31;
    const int cell   = blockIdx.x * 4 + warpId;      // grid sized exactly

    const int box = cell / CELLS_PER_BOX;            // const-div -> mul/shift
    const int pq  = cell - box * CELLS_PER_BOX;      // 0..48
    const int py  = pq / POOL;
    const int px  = pq - py * POOL;
    const int b   = box >> 9;                        // box / 512

    const float* roi = rois + box * 5;
    const float y1 = roi[0];
    const float x1 = roi[1];
    const float y2 = roi[2];
    const float x2 = roi[3];

    const bool lvl1 = ((y2 - y1) > LVL_THRESH) || ((x2 - x1) > LVL_THRESH);
    const float4* __restrict__ img4 = lvl1 ? feat1 : feat0;
    const int HW = lvl1 ? 128 : 256;                 // H == W at both levels
    const float HWm1 = (float)(HW - 1);

    const float ry = (float)py * (1.0f / 6.0f);
    const float rx = (float)px * (1.0f / 6.0f);
    const float ys = (y1 * INV_IMG + ry * (y2 - y1) * INV_IMG) * HWm1;
    const float xs = (x1 * INV_IMG + rx * (x2 - x1) * INV_IMG) * HWm1;

    float4* outp = out + cell * (CCH / 4) + lane * 2;

    const bool valid = (ys >= 0.0f) && (ys <= HWm1) &&
                       (xs >= 0.0f) && (xs <= HWm1);
    if (!valid) {
        const float4 z = make_float4(0.f, 0.f, 0.f, 0.f);
        outp[0] = z;
        outp[1] = z;
        return;
    }

    const float y0f = floorf(ys);
    const float x0f = floorf(xs);
    const float wy = ys - y0f;
    const float wx = xs - x0f;

    // valid => y0f,x0f already in [0, HW-1]; only far corner needs clamping
    const int iy0 = (int)y0f;
    const int ix0 = (int)x0f;
    const int iyp = min(iy0 + 1, HW - 1);
    const int ixp = min(ix0 + 1, HW - 1);

    // 32-bit offsets in float4 units
    const int base00 = ((b * HW + iy0) * HW + ix0) * (CCH / 4);
    const int dx = (ixp - ix0) * (CCH / 4);
    const int dy = (iyp - iy0) * HW * (CCH / 4);

    const float4* p = img4 + base00 + lane * 2;
    // 8 independent 16B loads (MLP=8)
    const float4 a00 = p[0];
    const float4 b00 = p[1];
    const float4 a01 = p[dx];
    const float4 b01 = p[dx + 1];
    const float4 a10 = p[dy];
    const float4 b10 = p[dy + 1];
    const float4 a11 = p[dy + dx];
    const float4 b11 = p[dy + dx + 1];

    const float4 r0 = lerp4(lerp4(a00, a01, wx), lerp4(a10, a11, wx), wy);
    const float4 r1 = lerp4(lerp4(b00, b01, wx), lerp4(b10, b11, wx), wy);

    outp[0] = r0;
    outp[1] = r1;
}

extern "C" void kernel_launch(void* const* d_in, const int* in_sizes, int n_in,
                              void* d_out, int out_size) {
    const float4* feat0 = (const float4*)d_in[0];
    const float4* feat1 = (const float4*)d_in[1];
    const float* rois   = (const float*)d_in[2];
    float4* out = (float4*)d_out;

    const int n_cells = NUM_B * NUM_R * CELLS_PER_BOX;   // 50176
    const int blocks = n_cells / 4;                      // 12544, exact
    roialign_kernel<<<blocks, 128>>>(feat0, feat1, rois, out);
}